// round 2
// baseline (speedup 1.0000x reference)
#include <cuda_runtime.h>
#include <cuda_fp16.h>
#include <cstdint>
#include <cstddef>

#define DI __device__ __forceinline__

static constexpr int NB  = 256;     // batch
static constexpr int CAT = 1024;
static constexpr int HD  = 512;
static constexpr int VOC = 32000;
static constexpr int TT  = 8;
static constexpr int G4  = 4 * HD;  // 2048

// ---------------- device scratch (static: no allocation) ----------------
__device__ __half d_ctxin_hi[NB * CAT];
__device__ __half d_ctxin_lo[NB * CAT];
__device__ __half d_wm_hi[HD * CAT];
__device__ __half d_wm_lo[HD * CAT];
__device__ __half d_wih_hi[G4 * HD];
__device__ __half d_wih_lo[G4 * HD];
__device__ __half d_whh16[G4 * HD];
__device__ __half d_wo16[VOC * HD];
__device__ float  d_ctx32[NB * HD];
__device__ __half d_ctx_hi[NB * HD];
__device__ __half d_ctx_lo[NB * HD];
__device__ float  d_xproj[NB * G4];
__device__ float  d_gates[NB * G4];
__device__ float  d_cst[NB * HD];
__device__ __half d_h_hi[NB * HD];
__device__ __half d_h_lo[NB * HD];
__device__ __half d_hall[NB * TT * HD];

// ---------------- PTX helpers ----------------
DI uint32_t smem_u32(const void* p) {
    uint32_t a;
    asm("{ .reg .u64 t; cvta.to.shared.u64 t, %1; cvt.u32.u64 %0, t; }"
        : "=r"(a) : "l"(p));
    return a;
}
DI void cp_async16(uint32_t dst, const void* src) {
    asm volatile("cp.async.cg.shared.global [%0], [%1], 16;"
                 :: "r"(dst), "l"(src) : "memory");
}
DI void cp_commit() { asm volatile("cp.async.commit_group;" ::: "memory"); }
template <int N>
DI void cp_wait() { asm volatile("cp.async.wait_group %0;" :: "n"(N) : "memory"); }

DI void ldsm_x4(uint32_t (&d)[4], uint32_t addr) {
    asm volatile("ldmatrix.sync.aligned.m8n8.x4.shared.b16 {%0,%1,%2,%3}, [%4];"
                 : "=r"(d[0]), "=r"(d[1]), "=r"(d[2]), "=r"(d[3]) : "r"(addr));
}
DI void mma16816(float (&c)[4], const uint32_t (&a)[4], uint32_t b0, uint32_t b1) {
    asm volatile(
        "mma.sync.aligned.m16n8k16.row.col.f32.f16.f16.f32 "
        "{%0,%1,%2,%3}, {%4,%5,%6,%7}, {%8,%9}, {%0,%1,%2,%3};"
        : "+f"(c[0]), "+f"(c[1]), "+f"(c[2]), "+f"(c[3])
        : "r"(a[0]), "r"(a[1]), "r"(a[2]), "r"(a[3]), "r"(b0), "r"(b1));
}

// ---------------- conversion kernels ----------------
__global__ void k_split(const float* __restrict__ x, __half* __restrict__ hi,
                        __half* __restrict__ lo, int n) {
    int i = blockIdx.x * blockDim.x + threadIdx.x;
    if (i < n) {
        float v = x[i];
        __half h = __float2half_rn(v);
        hi[i] = h;
        lo[i] = __float2half_rn(v - __half2float(h));
    }
}
__global__ void k_cvt(const float4* __restrict__ x, __half2* __restrict__ y, int n4) {
    int i = blockIdx.x * blockDim.x + threadIdx.x;
    if (i < n4) {
        float4 v = x[i];
        y[2 * i]     = __floats2half2_rn(v.x, v.y);
        y[2 * i + 1] = __floats2half2_rn(v.z, v.w);
    }
}

// ---------------- LSTM cell (elementwise) ----------------
__global__ void k_cell(const float* __restrict__ xp, const float* __restrict__ gt,
                       const float* __restrict__ bhh, float* __restrict__ c,
                       __half* __restrict__ hhi, __half* __restrict__ hlo,
                       __half* __restrict__ hall, int t) {
    int idx = blockIdx.x * blockDim.x + threadIdx.x;
    if (idx >= NB * HD) return;
    int n = idx / HD, j = idx - n * HD;
    size_t base = (size_t)n * G4 + j;
    float gi, gf, gg, go;
    if (t == 0) {  // gates GEMM skipped (h=0); GEMM would have added b_hh, add here
        gi = xp[base]          + bhh[j];
        gf = xp[base + HD]     + bhh[HD + j];
        gg = xp[base + 2 * HD] + bhh[2 * HD + j];
        go = xp[base + 3 * HD] + bhh[3 * HD + j];
    } else {       // gates = h@Whh^T + b_hh already
        gi = xp[base]          + gt[base];
        gf = xp[base + HD]     + gt[base + HD];
        gg = xp[base + 2 * HD] + gt[base + 2 * HD];
        go = xp[base + 3 * HD] + gt[base + 3 * HD];
    }
    float si = 1.f / (1.f + expf(-gi));
    float sf = 1.f / (1.f + expf(-gf));
    float tg = tanhf(gg);
    float so = 1.f / (1.f + expf(-go));
    float cp = (t == 0) ? 0.f : c[idx];
    float cn = sf * cp + si * tg;
    c[idx] = cn;
    float h = so * tanhf(cn);
    __half hh = __float2half_rn(h);
    hhi[idx] = hh;
    hlo[idx] = __float2half_rn(h - __half2float(hh));
    hall[((size_t)n * TT + t) * HD + j] = hh;
}

// ---------------- HMMA f16 GEMM: C[M,Ntot] = sum_p A_p[M,K] @ B_p[Ntot,K]^T + bias
// CTA tile 128x128, K-chunk 64, 256 threads (8 warps 4x2), warp tile 32x64.
// 2-stage cp.async double buffer; xor-swizzled SMEM; fp32 accum in regs.
template <int NPASS>
__global__ void __launch_bounds__(256)
k_gemm(float* __restrict__ C, int ldc,
       const __half* __restrict__ A0, const __half* __restrict__ A1,
       const __half* __restrict__ A2,
       const __half* __restrict__ B0, const __half* __restrict__ B1,
       const __half* __restrict__ B2,
       const float* __restrict__ bias, int K) {
    extern __shared__ char smem[];
    constexpr int TILE_B = 128 * 128;     // 128 rows x 64 halfs = 16 KB
    constexpr int STG    = 2 * TILE_B;    // A + B per stage

    const uint32_t sb = smem_u32(smem);
    const int tid    = threadIdx.x;
    const int lane   = tid & 31;
    const int wid    = tid >> 5;
    const int warp_m = wid & 3;   // 4 M-slices of 32
    const int warp_n = wid >> 2;  // 2 N-slices of 64

    const __half* Ap[3] = {A0, A1, A2};
    const __half* Bp[3] = {B0, B1, B2};

    const int mBase = blockIdx.y * 128;
    const int nBase = blockIdx.x * 128;
    const int kch   = K >> 6;
    const int total = NPASS * kch;

    // per-thread load indices: 4 x 16B groups for A, 4 for B
    const int ldr = tid >> 3;        // base row (stride 32 over 4 iters)
    const int ldg = tid & 7;         // 16B group in row (0..7)

    auto load_chunk = [&](int ch) {
        const int st   = ch & 1;
        const int pass = ch / kch;
        const int kc   = ch - pass * kch;
        const __half* Ag = Ap[pass] + (size_t)mBase * K + kc * 64;
        const __half* Bg = Bp[pass] + (size_t)nBase * K + kc * 64;
        const uint32_t a_u = sb + st * STG;
        const uint32_t b_u = a_u + TILE_B;
#pragma unroll
        for (int it = 0; it < 4; ++it) {
            int r = ldr + it * 32;
            uint32_t off = (uint32_t)(r * 128 + (ldg * 16 ^ ((r & 7) << 4)));
            cp_async16(a_u + off, Ag + (size_t)r * K + ldg * 8);
            cp_async16(b_u + off, Bg + (size_t)r * K + ldg * 8);
        }
        cp_commit();
    };

    float acc[2][8][4];
#pragma unroll
    for (int mi = 0; mi < 2; ++mi)
#pragma unroll
        for (int ni = 0; ni < 8; ++ni)
#pragma unroll
            for (int q = 0; q < 4; ++q) acc[mi][ni][q] = 0.f;

    // precompute per-lane ldmatrix row components
    int arow[2], brow[4];
#pragma unroll
    for (int mi = 0; mi < 2; ++mi)
        arow[mi] = warp_m * 32 + mi * 16 + (lane & 7) + ((lane >> 3) & 1) * 8;
#pragma unroll
    for (int nq = 0; nq < 4; ++nq)
        brow[nq] = warp_n * 64 + nq * 16 + (lane & 7) + (lane >> 4) * 8;
    const int akb = (lane >> 4) * 16;        // A k-byte sub-offset
    const int bkb = ((lane >> 3) & 1) * 16;  // B k-byte sub-offset

    load_chunk(0);

    for (int ch = 0; ch < total; ++ch) {
        if (ch + 1 < total) { load_chunk(ch + 1); cp_wait<1>(); }
        else                { cp_wait<0>(); }
        __syncthreads();

        const uint32_t a_u = sb + (ch & 1) * STG;
        const uint32_t b_u = a_u + TILE_B;

#pragma unroll
        for (int ks = 0; ks < 4; ++ks) {
            uint32_t aF[2][4];
#pragma unroll
            for (int mi = 0; mi < 2; ++mi) {
                int r  = arow[mi];
                int kb = ks * 32 + akb;
                ldsm_x4(aF[mi], a_u + r * 128 + (kb ^ ((r & 7) << 4)));
            }
            uint32_t bF[4][4];  // bF[nq] = frags for n-tiles 2nq, 2nq+1
#pragma unroll
            for (int nq = 0; nq < 4; ++nq) {
                int r  = brow[nq];
                int kb = ks * 32 + bkb;
                ldsm_x4(bF[nq], b_u + r * 128 + (kb ^ ((r & 7) << 4)));
            }
#pragma unroll
            for (int mi = 0; mi < 2; ++mi)
#pragma unroll
                for (int ni = 0; ni < 8; ++ni)
                    mma16816(acc[mi][ni], aF[mi],
                             bF[ni >> 1][(ni & 1) * 2], bF[ni >> 1][(ni & 1) * 2 + 1]);
        }
        __syncthreads();
    }

    // ---- epilogue: bias add + store
    const int m0 = mBase + warp_m * 32;
    const int n0 = nBase + warp_n * 64;
#pragma unroll
    for (int ni = 0; ni < 8; ++ni) {
        int col = n0 + ni * 8 + 2 * (lane & 3);
        float2 bv = *reinterpret_cast<const float2*>(bias + col);
#pragma unroll
        for (int mi = 0; mi < 2; ++mi) {
            int row = m0 + mi * 16 + (lane >> 2);
            float2 v0 = {acc[mi][ni][0] + bv.x, acc[mi][ni][1] + bv.y};
            float2 v1 = {acc[mi][ni][2] + bv.x, acc[mi][ni][3] + bv.y};
            *reinterpret_cast<float2*>(C + (size_t)row * ldc + col) = v0;
            *reinterpret_cast<float2*>(C + (size_t)(row + 8) * ldc + col) = v1;
        }
    }
}

// ---------------- host orchestration ----------------
extern "C" void kernel_launch(void* const* d_in, const int* in_sizes, int n_in,
                              void* d_out, int out_size) {
    const float* context = (const float*)d_in[0];
    const float* W_merge = (const float*)d_in[1];
    const float* b_merge = (const float*)d_in[2];
    const float* W_ih    = (const float*)d_in[3];
    const float* W_hh    = (const float*)d_in[4];
    const float* b_ih    = (const float*)d_in[5];
    const float* b_hh    = (const float*)d_in[6];
    const float* W_out   = (const float*)d_in[7];
    const float* b_out   = (const float*)d_in[8];
    float* out = (float*)d_out;

    __half *ctxin_hi, *ctxin_lo, *wm_hi, *wm_lo, *wih_hi, *wih_lo, *whh16, *wo16;
    __half *ctx_hi, *ctx_lo, *h_hi, *h_lo, *hall;
    float *ctx32, *xproj, *gates, *cbuf;
    cudaGetSymbolAddress((void**)&ctxin_hi, d_ctxin_hi);
    cudaGetSymbolAddress((void**)&ctxin_lo, d_ctxin_lo);
    cudaGetSymbolAddress((void**)&wm_hi, d_wm_hi);
    cudaGetSymbolAddress((void**)&wm_lo, d_wm_lo);
    cudaGetSymbolAddress((void**)&wih_hi, d_wih_hi);
    cudaGetSymbolAddress((void**)&wih_lo, d_wih_lo);
    cudaGetSymbolAddress((void**)&whh16, d_whh16);
    cudaGetSymbolAddress((void**)&wo16, d_wo16);
    cudaGetSymbolAddress((void**)&ctx32, d_ctx32);
    cudaGetSymbolAddress((void**)&ctx_hi, d_ctx_hi);
    cudaGetSymbolAddress((void**)&ctx_lo, d_ctx_lo);
    cudaGetSymbolAddress((void**)&xproj, d_xproj);
    cudaGetSymbolAddress((void**)&gates, d_gates);
    cudaGetSymbolAddress((void**)&cbuf, d_cst);
    cudaGetSymbolAddress((void**)&h_hi, d_h_hi);
    cudaGetSymbolAddress((void**)&h_lo, d_h_lo);
    cudaGetSymbolAddress((void**)&hall, d_hall);

    const int SMEM = 2 * 2 * 128 * 128;  // 65536
    cudaFuncSetAttribute(k_gemm<1>, cudaFuncAttributeMaxDynamicSharedMemorySize, SMEM);
    cudaFuncSetAttribute(k_gemm<2>, cudaFuncAttributeMaxDynamicSharedMemorySize, SMEM);
    cudaFuncSetAttribute(k_gemm<3>, cudaFuncAttributeMaxDynamicSharedMemorySize, SMEM);

    // conversions / splits
    k_split<<<(NB * CAT + 255) / 256, 256>>>(context, ctxin_hi, ctxin_lo, NB * CAT);
    k_split<<<(HD * CAT + 255) / 256, 256>>>(W_merge, wm_hi, wm_lo, HD * CAT);
    k_split<<<(G4 * HD + 255) / 256, 256>>>(W_ih, wih_hi, wih_lo, G4 * HD);
    k_cvt<<<(G4 * HD / 4 + 255) / 256, 256>>>((const float4*)W_hh, (__half2*)whh16, G4 * HD / 4);
    k_cvt<<<(VOC * HD / 4 + 255) / 256, 256>>>((const float4*)W_out, (__half2*)wo16, VOC * HD / 4);

    // GEMM1: ctx = context @ Wm^T + b_merge   (3-pass split-fp16 ~ fp32)
    {
        dim3 g(HD / 128, NB / 128);  // (4,2)
        k_gemm<3><<<g, 256, SMEM>>>(ctx32, HD,
            ctxin_hi, ctxin_lo, ctxin_hi,
            wm_hi, wm_hi, wm_lo,
            b_merge, CAT);
    }
    k_split<<<(NB * HD + 255) / 256, 256>>>(ctx32, ctx_hi, ctx_lo, NB * HD);
    // GEMM2: x_proj = ctx @ Wih^T + b_ih   (3-pass)
    {
        dim3 g(G4 / 128, NB / 128);  // (16,2)
        k_gemm<3><<<g, 256, SMEM>>>(xproj, G4,
            ctx_hi, ctx_lo, ctx_hi,
            wih_hi, wih_hi, wih_lo,
            b_ih, HD);
    }
    // LSTM recurrence (T sequential steps)
    for (int t = 0; t < TT; ++t) {
        if (t > 0) {
            dim3 g(G4 / 128, NB / 128);  // (16,2)
            k_gemm<2><<<g, 256, SMEM>>>(gates, G4,
                h_hi, h_lo, h_hi,
                whh16, whh16, whh16,
                b_hh, HD);
        }
        k_cell<<<(NB * HD + 255) / 256, 256>>>(xproj, gates, b_hh, cbuf,
                                               h_hi, h_lo, hall, t);
    }
    // GEMM4 (the big one): out[2048,32000] = H_all @ Wo^T + b_out
    {
        dim3 g(VOC / 128, (NB * TT) / 128);  // (250,16)
        k_gemm<1><<<g, 256, SMEM>>>(out, VOC,
            hall, hall, hall,
            wo16, wo16, wo16,
            b_out, HD);
    }
}